// round 3
// baseline (speedup 1.0000x reference)
#include <cuda_runtime.h>
#include <math.h>
#include <stdint.h>

#define KT 64
#define VV 50000
#define DD 128
#define BB 8192
#define LL 126
#define BOS 62
#define EOS 63

// Scratch (static __device__ — no allocations allowed)
__device__ float g_A[KT * KT];          // A[i][j] transition probs (row softmax of WA, col BOS = 0)
__device__ float g_Z[KT];               // per-tag emission partition sums
__device__ __align__(16) float g_invZ[KT];
__device__ float g_Bt[(size_t)VV * KT]; // exp(theta_k . E_v), layout [v][k] (256B rows)

// ---------------------------------------------------------------------------
// Kernel 1: transition softmax + zero Z accumulators
// ---------------------------------------------------------------------------
__global__ void k_trans(const float* __restrict__ WA) {
    __shared__ float w[KT * KT];
    for (int idx = threadIdx.x; idx < KT * KT; idx += 256) w[idx] = WA[idx];
    __syncthreads();
    int i = threadIdx.x;
    if (i < KT) {
        float m = -1e30f;
        for (int j = 0; j < KT; j++)
            if (j != BOS) m = fmaxf(m, w[i * KT + j]);
        float ssum = 0.f;
        for (int j = 0; j < KT; j++)
            if (j != BOS) ssum += __expf(w[i * KT + j] - m);
        float inv = 1.f / ssum;
        for (int j = 0; j < KT; j++)
            g_A[i * KT + j] = (j == BOS) ? 0.f : __expf(w[i * KT + j] - m) * inv;
        g_Z[i] = 0.f;
    }
}

// ---------------------------------------------------------------------------
// Kernel 2: emission table  g_Bt[v][k] = exp(theta_k . E_v), accumulate Z[k].
// Block = 256 threads = 4 groups x 64 tags; each block owns 64 consecutive v.
// Logits are tiny (|.| <~ 1.5) so exp without max-subtraction is safe.
// ---------------------------------------------------------------------------
__global__ void k_emit(const float* __restrict__ ThetaB, const float* __restrict__ E) {
    __shared__ float2 th2[KT][DD / 2 + 1];            // padded: conflict-light
    __shared__ __align__(16) float Esh[4][DD];
    int tid = threadIdx.x;
    for (int idx = tid; idx < KT * DD / 2; idx += 256) {
        int k = idx >> 6, d2 = idx & 63;
        th2[k][d2] = ((const float2*)ThetaB)[idx];
    }
    __syncthreads();
    int g = tid >> 6;      // group 0..3
    int k = tid & 63;      // tag
    float zacc = 0.f;
    int vbase = blockIdx.x * 64;
    for (int it = 0; it < 16; it++) {
        int v = vbase + it * 4 + g;
        if (v < VV) {
            const float2* er = (const float2*)(E + (size_t)v * DD);
            ((float2*)Esh[g])[k] = er[k];             // 64 threads load one E row
        }
        __syncthreads();
        if (v < VV) {
            float dot = 0.f;
            const float2* ev = (const float2*)Esh[g];
#pragma unroll 8
            for (int d2 = 0; d2 < DD / 2; d2++) {
                float2 t = th2[k][d2];
                float2 e = ev[d2];
                dot = fmaf(t.x, e.x, dot);
                dot = fmaf(t.y, e.y, dot);
            }
            float p = __expf(dot);
            g_Bt[(size_t)v * KT + k] = p;
            zacc += p;
        }
        __syncthreads();
    }
    atomicAdd(&g_Z[k], zacc);
}

// ---------------------------------------------------------------------------
// Kernel 3: invZ (fold softmax normalizer into forward pass); BOS/EOS emit 0.
// ---------------------------------------------------------------------------
__global__ void k_invz() {
    int k = threadIdx.x;
    if (k < KT) g_invZ[k] = (k >= BOS) ? 0.f : (1.f / g_Z[k]);
}

// ---------------------------------------------------------------------------
// Kernel 4: forward recursion in scaled-probability domain.
// Block = 64 threads: 16 sentences x 4 tag-blocks of 16 tags. Grid = 512
// (-> ~3.5 blocks/SM, 2 warps/block: cheap per-step barrier, decent
// latency hiding while staying FFMA-throughput-bound).
// A held in shared with a 4x4 column-group transpose (involution on base-4
// digits of the column group) so the 4 tag-block lanes read disjoint bank
// quarters: conflict-free LDS.128 with 8-way multicast.
// Per step: q = A^T p (64x16 FMA/thread), p' = q * em * invZ, power-of-two
// rescale (bit-math frexp), double-buffered p in shared (1 barrier/step).
// Emission gathers for step t+1 are prefetched during step t's mat-vec.
// ---------------------------------------------------------------------------
__global__ void __launch_bounds__(64) k_forward(const int* __restrict__ words,
                                                float* __restrict__ out) {
    __shared__ __align__(16) float Ash[KT][KT];   // permuted columns
    __shared__ float psh[2][KT][17];              // p[tag][sent], padded
    int tid = threadIdx.x;
    int s   = tid >> 2;        // sentence slot 0..15
    int t4  = tid & 3;         // tag block 0..3
    int j0  = t4 << 4;
    int b   = blockIdx.x * 16 + s;

    // Load A with column-group transpose: group gq=j>>2 stored at
    // pos = (gq&3)*4 + (gq>>2)  (column 63 / EOS is a fixed point).
    for (int idx = tid; idx < KT * KT; idx += 64) {
        int i = idx >> 6, j = idx & 63;
        int gq = j >> 2, u = j & 3;
        int pos = ((gq & 3) << 2) + (gq >> 2);
        Ash[i][(pos << 2) + u] = g_A[idx];
    }
    if (tid < 16) {
        for (int i = 0; i < KT; i++) psh[0][i][tid] = (i == BOS) ? 1.f : 0.f;
    }
    float4 iz0 = ((const float4*)g_invZ)[(t4 << 2) + 0];
    float4 iz1 = ((const float4*)g_invZ)[(t4 << 2) + 1];
    float4 iz2 = ((const float4*)g_invZ)[(t4 << 2) + 2];
    float4 iz3 = ((const float4*)g_invZ)[(t4 << 2) + 3];
    __syncthreads();

    const int* wrow = words + b * LL;
    int wcur = wrow[0];
    const float4* bt0 = (const float4*)(g_Bt + (size_t)wcur * KT);
    float4 e0 = bt0[(t4 << 2) + 0];
    float4 e1 = bt0[(t4 << 2) + 1];
    float4 e2 = bt0[(t4 << 2) + 2];
    float4 e3 = bt0[(t4 << 2) + 3];
    int wnext = wrow[1];

    int S = 0;
    int buf = 0;
    float pf[16];

    for (int step = 0; step < LL; step++) {
        // Prefetch next step's emission row + the word after that.
        float4 n0, n1, n2, n3;
        int wnn = 0;
        if (step < LL - 1) {
            const float4* btn = (const float4*)(g_Bt + (size_t)wnext * KT);
            n0 = btn[(t4 << 2) + 0];
            n1 = btn[(t4 << 2) + 1];
            n2 = btn[(t4 << 2) + 2];
            n3 = btn[(t4 << 2) + 3];
            if (step < LL - 2) wnn = wrow[step + 2];
        }

        // q = A^T p for this thread's 16 tags (register r <-> tag j0+r)
        float q[16];
#pragma unroll
        for (int r = 0; r < 16; r++) q[r] = 0.f;
        const float (*pb)[17] = psh[buf];
#pragma unroll 8
        for (int i = 0; i < KT; i++) {
            float pi = pb[i][s];
            const float4* ar = (const float4*)Ash[i];
            float4 a0 = ar[t4];
            float4 a1 = ar[4 + t4];
            float4 a2 = ar[8 + t4];
            float4 a3 = ar[12 + t4];
            q[0]  = fmaf(pi, a0.x, q[0]);
            q[1]  = fmaf(pi, a0.y, q[1]);
            q[2]  = fmaf(pi, a0.z, q[2]);
            q[3]  = fmaf(pi, a0.w, q[3]);
            q[4]  = fmaf(pi, a1.x, q[4]);
            q[5]  = fmaf(pi, a1.y, q[5]);
            q[6]  = fmaf(pi, a1.z, q[6]);
            q[7]  = fmaf(pi, a1.w, q[7]);
            q[8]  = fmaf(pi, a2.x, q[8]);
            q[9]  = fmaf(pi, a2.y, q[9]);
            q[10] = fmaf(pi, a2.z, q[10]);
            q[11] = fmaf(pi, a2.w, q[11]);
            q[12] = fmaf(pi, a3.x, q[12]);
            q[13] = fmaf(pi, a3.y, q[13]);
            q[14] = fmaf(pi, a3.z, q[14]);
            q[15] = fmaf(pi, a3.w, q[15]);
        }

        // p' = q * em * invZ; track max for rescale
        pf[0]  = q[0]  * e0.x * iz0.x;
        pf[1]  = q[1]  * e0.y * iz0.y;
        pf[2]  = q[2]  * e0.z * iz0.z;
        pf[3]  = q[3]  * e0.w * iz0.w;
        pf[4]  = q[4]  * e1.x * iz1.x;
        pf[5]  = q[5]  * e1.y * iz1.y;
        pf[6]  = q[6]  * e1.z * iz1.z;
        pf[7]  = q[7]  * e1.w * iz1.w;
        pf[8]  = q[8]  * e2.x * iz2.x;
        pf[9]  = q[9]  * e2.y * iz2.y;
        pf[10] = q[10] * e2.z * iz2.z;
        pf[11] = q[11] * e2.w * iz2.w;
        pf[12] = q[12] * e3.x * iz3.x;
        pf[13] = q[13] * e3.y * iz3.y;
        pf[14] = q[14] * e3.z * iz3.z;
        pf[15] = q[15] * e3.w * iz3.w;

        float pm = 0.f;
#pragma unroll
        for (int r = 0; r < 16; r++) pm = fmaxf(pm, pf[r]);
        // max across the 4 tag-block lanes of this sentence (consecutive lanes)
        pm = fmaxf(pm, __shfl_xor_sync(0xffffffffu, pm, 1));
        pm = fmaxf(pm, __shfl_xor_sync(0xffffffffu, pm, 2));

        // power-of-two rescale: pm = f * 2^e, f in [0.5,1)
        int e = 0;
        if (pm > 0.f) e = ((__float_as_int(pm) >> 23) & 255) - 126;
        S += e;
        float sc = __int_as_float((127 - e) << 23);

        float (*pw)[17] = psh[buf ^ 1];
#pragma unroll
        for (int r = 0; r < 16; r++) {
            pf[r] *= sc;
            pw[j0 + r][s] = pf[r];
        }
        buf ^= 1;
        __syncthreads();

        e0 = n0; e1 = n1; e2 = n2; e3 = n3;
        wnext = wnn;
    }

    // Final transition into EOS (column 63 of A; fixed point of permutation)
    float part = 0.f;
#pragma unroll
    for (int r = 0; r < 16; r++) part = fmaf(pf[r], Ash[j0 + r][EOS], part);
    part += __shfl_xor_sync(0xffffffffu, part, 1);
    part += __shfl_xor_sync(0xffffffffu, part, 2);
    if (t4 == 0) out[b] = __logf(part) + (float)S * 0.6931471805599453f;
}

// ---------------------------------------------------------------------------
extern "C" void kernel_launch(void* const* d_in, const int* in_sizes, int n_in,
                              void* d_out, int out_size) {
    // Identify inputs by element count (all four are distinct):
    //   words: 8192*126 = 1032192 (int32)
    //   ThetaB: 64*128  = 8192    (f32)
    //   WA:     64*64   = 4096    (f32)
    //   E:      50000*128 = 6400000 (f32)
    const int* words = nullptr;
    const float* ThetaB = nullptr;
    const float* WA = nullptr;
    const float* E = nullptr;
    for (int i = 0; i < n_in; i++) {
        switch (in_sizes[i]) {
            case BB * LL:   words  = (const int*)d_in[i];   break;
            case KT * DD:   ThetaB = (const float*)d_in[i]; break;
            case KT * KT:   WA     = (const float*)d_in[i]; break;
            case VV * DD:   E      = (const float*)d_in[i]; break;
            default: break;
        }
    }

    k_trans<<<1, 256>>>(WA);
    k_emit<<<(VV + 63) / 64, 256>>>(ThetaB, E);
    k_invz<<<1, 64>>>();
    k_forward<<<BB / 16, 64>>>(words, (float*)d_out);
}

// round 4
// speedup vs baseline: 1.8696x; 1.8696x over previous
#include <cuda_runtime.h>
#include <math.h>
#include <stdint.h>

#define KT 64
#define VV 50000
#define DD 128
#define BB 8192
#define LL 126
#define BOS 62
#define EOS 63

typedef unsigned long long ull;

// Scratch (static __device__ — no allocations allowed)
__device__ float g_A[KT * KT];          // raw transition probs (row softmax of WA, col BOS = 0)
__device__ float g_As[KT * KT];         // invZ-folded + column-permuted A for forward pass
__device__ float g_Z[KT];               // per-tag emission partition sums
__device__ float g_Bt[(size_t)VV * KT]; // exp(theta_k . E_v), layout [v][k] (256B rows)

// ---- packed f32x2 helpers ----------------------------------------------------
__device__ __forceinline__ ull fma2(ull a, ull b, ull c) {
    ull d;
    asm("fma.rn.f32x2 %0, %1, %2, %3;" : "=l"(d) : "l"(a), "l"(b), "l"(c));
    return d;
}
__device__ __forceinline__ ull mul2(ull a, ull b) {
    ull d;
    asm("mul.rn.f32x2 %0, %1, %2;" : "=l"(d) : "l"(a), "l"(b));
    return d;
}
__device__ __forceinline__ ull packdup(float x) {
    ull d;
    asm("mov.b64 %0, {%1, %1};" : "=l"(d) : "f"(x));
    return d;
}
__device__ __forceinline__ void unpack2(ull v, float& lo, float& hi) {
    asm("mov.b64 {%0, %1}, %2;" : "=f"(lo), "=f"(hi) : "l"(v));
}

// ---------------------------------------------------------------------------
// Kernel 1: transition softmax + zero Z accumulators
// ---------------------------------------------------------------------------
__global__ void k_trans(const float* __restrict__ WA) {
    __shared__ float w[KT * KT];
    for (int idx = threadIdx.x; idx < KT * KT; idx += 256) w[idx] = WA[idx];
    __syncthreads();
    int i = threadIdx.x;
    if (i < KT) {
        float m = -1e30f;
        for (int j = 0; j < KT; j++)
            if (j != BOS) m = fmaxf(m, w[i * KT + j]);
        float ssum = 0.f;
        for (int j = 0; j < KT; j++)
            if (j != BOS) ssum += __expf(w[i * KT + j] - m);
        float inv = 1.f / ssum;
        for (int j = 0; j < KT; j++)
            g_A[i * KT + j] = (j == BOS) ? 0.f : __expf(w[i * KT + j] - m) * inv;
        g_Z[i] = 0.f;
    }
}

// ---------------------------------------------------------------------------
// Kernel 2: emission table  g_Bt[v][k] = exp(theta_k . E_v), accumulate Z[k].
// ---------------------------------------------------------------------------
__global__ void k_emit(const float* __restrict__ ThetaB, const float* __restrict__ E) {
    __shared__ float2 th2[KT][DD / 2 + 1];
    __shared__ __align__(16) float Esh[4][DD];
    int tid = threadIdx.x;
    for (int idx = tid; idx < KT * DD / 2; idx += 256) {
        int k = idx >> 6, d2 = idx & 63;
        th2[k][d2] = ((const float2*)ThetaB)[idx];
    }
    __syncthreads();
    int g = tid >> 6;
    int k = tid & 63;
    float zacc = 0.f;
    int vbase = blockIdx.x * 64;
    for (int it = 0; it < 16; it++) {
        int v = vbase + it * 4 + g;
        if (v < VV) {
            const float2* er = (const float2*)(E + (size_t)v * DD);
            ((float2*)Esh[g])[k] = er[k];
        }
        __syncthreads();
        if (v < VV) {
            float dot = 0.f;
            const float2* ev = (const float2*)Esh[g];
#pragma unroll 8
            for (int d2 = 0; d2 < DD / 2; d2++) {
                float2 t = th2[k][d2];
                float2 e = ev[d2];
                dot = fmaf(t.x, e.x, dot);
                dot = fmaf(t.y, e.y, dot);
            }
            float p = __expf(dot);
            g_Bt[(size_t)v * KT + k] = p;
            zacc += p;
        }
        __syncthreads();
    }
    atomicAdd(&g_Z[k], zacc);
}

// ---------------------------------------------------------------------------
// Kernel 3: fold invZ into A's columns + permute columns for conflict-free
// forward loads. Column j (tag j, group gq=j>>3, m=j&7) goes to position
// pos = m<4 ? 4*gq+m : 32+4*gq+(m-4)  (bijection; lane g's two float4 chunks
// at words 4g and 32+4g then cover tags 8g..8g+3 and 8g+4..8g+7, and the 8
// lanes' chunks tile 32 consecutive banks -> conflict-free LDS.128).
// BOS/EOS columns get invZ=0 (emission prob 0 at those tags).
// ---------------------------------------------------------------------------
__global__ void k_scaleA() {
    int j = threadIdx.x;
    if (j < KT) {
        float iz = (j >= BOS) ? 0.f : (1.f / g_Z[j]);
        int gq = j >> 3, m = j & 7;
        int pos = (m < 4) ? (gq * 4 + m) : (32 + gq * 4 + (m - 4));
        for (int i = 0; i < KT; i++)
            g_As[i * KT + pos] = g_A[i * KT + j] * iz;
    }
}

// ---------------------------------------------------------------------------
// Kernel 4: forward recursion, scaled-probability domain, packed f32x2 FMA.
// Block = 64 threads = 2 independent warps (share read-only Ash only).
// Warp: lane = 4*g + ss; g=0..7 owns tags 8g..8g+7; ss=0..3 owns sentences
// 4ss..4ss+3  -> 16 sentences/warp, 32/block, grid 256.
// p kept DUPLICATED in shared as (p,p) u64 pairs, rows permuted by
// rowp(tag)=8*(tag&7)+(tag>>3), row stride 21 u64 (42 words): inner-loop
// consumption is broadcast LDS.64, stores are ~2-way-conflict STS.64.
// Inner loop per prev-tag i: 2 LDS.128 (A pairs) + 4 LDS.64 (p dup) +
// 16 fma.rn.f32x2 (8 tags x 4 sentences).
// Per-sentence power-of-two rescale; invZ already folded into A.
// ---------------------------------------------------------------------------
__global__ void __launch_bounds__(64) k_forward(const int* __restrict__ words,
                                                float* __restrict__ out) {
    __shared__ __align__(16) float Ash[KT][KT];
    __shared__ ull pd[2][2][KT][21];   // [warp][buf][rowp][sent] duplicated pairs
    int tid  = threadIdx.x;
    int wid  = tid >> 5;
    int lane = tid & 31;
    int g    = lane >> 2;   // tag group
    int ss   = lane & 3;    // sentence slot

    for (int idx = tid; idx < KT * KT; idx += 64)
        Ash[idx >> 6][idx & 63] = g_As[idx];
    __syncthreads();

    int sbase = blockIdx.x * 32 + wid * 16 + ss * 4;  // first of this lane's 4 sentences
    const int* wr = words + (size_t)sbase * LL;

    // initial p: one-hot at BOS tag (62 = 8*7+6 -> g==7, r==6)
#pragma unroll
    for (int r = 0; r < 8; r++) {
        float v = (g == 7 && r == 6) ? 1.f : 0.f;
        ull pv = packdup(v);
#pragma unroll
        for (int c = 0; c < 4; c++) pd[wid][0][8 * r + g][ss * 4 + c] = pv;
    }
    __syncwarp();

    int wn[4];
#pragma unroll
    for (int c = 0; c < 4; c++) wn[c] = wr[c * LL];

    int S[4] = {0, 0, 0, 0};
    int buf = 0;
    float f[8][4];

    for (int step = 0; step < LL; step++) {
        // issue this step's emission loads early (L2 latency hidden by matvec)
        ull ee[4][4];
#pragma unroll
        for (int c = 0; c < 4; c++) {
            const ulonglong2* ep =
                (const ulonglong2*)(g_Bt + (size_t)wn[c] * KT + g * 8);
            ulonglong2 t0 = ep[0], t1 = ep[1];
            ee[c][0] = t0.x; ee[c][1] = t0.y; ee[c][2] = t1.x; ee[c][3] = t1.y;
        }
        if (step < LL - 1) {
#pragma unroll
            for (int c = 0; c < 4; c++) wn[c] = wr[c * LL + step + 1];
        }

        // q = A^T p  (packed over adjacent tag pairs)
        ull q[4][4];
#pragma unroll
        for (int pp = 0; pp < 4; pp++)
#pragma unroll
            for (int c = 0; c < 4; c++) q[pp][c] = 0ull;

#pragma unroll
        for (int i = 0; i < KT; i++) {
            const float* ar = Ash[i];
            ulonglong2 a0 = *(const ulonglong2*)(ar + 4 * g);        // tags 8g..8g+3
            ulonglong2 a1 = *(const ulonglong2*)(ar + 32 + 4 * g);   // tags 8g+4..8g+7
            int rp = ((i & 7) << 3) + (i >> 3);
#pragma unroll
            for (int c = 0; c < 4; c++) {
                ull pv = pd[wid][buf][rp][ss * 4 + c];
                q[0][c] = fma2(a0.x, pv, q[0][c]);
                q[1][c] = fma2(a0.y, pv, q[1][c]);
                q[2][c] = fma2(a1.x, pv, q[2][c]);
                q[3][c] = fma2(a1.y, pv, q[3][c]);
            }
        }

        // p' = q * em (invZ already in A); unpack for max/rescale/store
#pragma unroll
        for (int pp = 0; pp < 4; pp++)
#pragma unroll
            for (int c = 0; c < 4; c++) {
                ull pf = mul2(q[pp][c], ee[c][pp]);
                unpack2(pf, f[2 * pp][c], f[2 * pp + 1][c]);
            }

        int nb = buf ^ 1;
#pragma unroll
        for (int c = 0; c < 4; c++) {
            float pm = 0.f;
#pragma unroll
            for (int r = 0; r < 8; r++) pm = fmaxf(pm, f[r][c]);
            pm = fmaxf(pm, __shfl_xor_sync(0xffffffffu, pm, 4));
            pm = fmaxf(pm, __shfl_xor_sync(0xffffffffu, pm, 8));
            pm = fmaxf(pm, __shfl_xor_sync(0xffffffffu, pm, 16));
            int e = 0;
            if (pm > 0.f) e = ((__float_as_int(pm) >> 23) & 255) - 126;
            S[c] += e;
            float sc = __int_as_float((127 - e) << 23);
#pragma unroll
            for (int r = 0; r < 8; r++) {
                f[r][c] *= sc;
                pd[wid][nb][8 * r + g][ss * 4 + c] = packdup(f[r][c]);
            }
        }
        buf = nb;
        __syncwarp();
    }

    // final transition into EOS using the UNSCALED A column
    float aeos[8];
#pragma unroll
    for (int r = 0; r < 8; r++) aeos[r] = g_A[(8 * g + r) * KT + EOS];
#pragma unroll
    for (int c = 0; c < 4; c++) {
        float part = 0.f;
#pragma unroll
        for (int r = 0; r < 8; r++) part = fmaf(f[r][c], aeos[r], part);
        part += __shfl_xor_sync(0xffffffffu, part, 4);
        part += __shfl_xor_sync(0xffffffffu, part, 8);
        part += __shfl_xor_sync(0xffffffffu, part, 16);
        if (g == 0)
            out[sbase + c] = __logf(part) + (float)S[c] * 0.6931471805599453f;
    }
}

// ---------------------------------------------------------------------------
extern "C" void kernel_launch(void* const* d_in, const int* in_sizes, int n_in,
                              void* d_out, int out_size) {
    const int* words = nullptr;
    const float* ThetaB = nullptr;
    const float* WA = nullptr;
    const float* E = nullptr;
    for (int i = 0; i < n_in; i++) {
        switch (in_sizes[i]) {
            case BB * LL:   words  = (const int*)d_in[i];   break;
            case KT * DD:   ThetaB = (const float*)d_in[i]; break;
            case KT * KT:   WA     = (const float*)d_in[i]; break;
            case VV * DD:   E      = (const float*)d_in[i]; break;
            default: break;
        }
    }

    k_trans<<<1, 256>>>(WA);
    k_emit<<<(VV + 63) / 64, 256>>>(ThetaB, E);
    k_scaleA<<<1, 64>>>();
    k_forward<<<BB / 32, 64>>>(words, (float*)d_out);
}